// round 16
// baseline (speedup 1.0000x reference)
#include <cuda_runtime.h>
#include <cfloat>

#define N_TOK    16384
#define KCODES   8192
#define HALF_K   4096
#define DIMD     64
#define ENC_CH   512
#define DEC_CH   512
#define OUT_MAIN (16*512*32*32)   /* 8388608 */

// ---------------- device scratch (no allocs allowed) ----------------
__device__ float g_wint[ENC_CH*DIMD];    // [c][d]   transposed w_in
__device__ float g_woutt[DIMD*DEC_CH];   // [d][o]   transposed w_out
__device__ float g_et[DIMD*KCODES];      // [d][k]   transposed embedding
__device__ float g_cn[KCODES];           // ||e_k||^2
__device__ float g_zt[DIMD*N_TOK];       // [d][n]   encoder output
__device__ float g_dec[KCODES*DEC_CH];   // [k][o]   decoded codebook
__device__ float g_bs[2*N_TOK];          // per-half best score
__device__ int   g_bi[2*N_TOK];          // per-half best index

typedef unsigned long long u64;

__device__ __forceinline__ u64 pack2(float lo, float hi){
    u64 r; asm("mov.b64 %0, {%1, %2};" : "=l"(r) : "f"(lo), "f"(hi)); return r;
}
__device__ __forceinline__ void unpack2(u64 v, float &lo, float &hi){
    asm("mov.b64 {%0, %1}, %2;" : "=f"(lo), "=f"(hi) : "l"(v));
}
__device__ __forceinline__ void fma2(u64 &d, u64 a, u64 b){
    asm("fma.rn.f32x2 %0, %1, %2, %3;" : "=l"(d) : "l"(a), "l"(b), "l"(d));
}

// ---------------- prep: transposes + codebook norms ----------------
__global__ __launch_bounds__(256) void prep_kernel(
    const float* __restrict__ w_in, const float* __restrict__ w_out,
    const float* __restrict__ emb)
{
    int i = blockIdx.x * 256 + threadIdx.x;
    if (i < ENC_CH*DIMD) {
        int c = i >> 6, d = i & 63;
        g_wint[i] = w_in[d*ENC_CH + c];
    } else if (i < ENC_CH*DIMD + DIMD*DEC_CH) {
        int j = i - ENC_CH*DIMD;
        int d = j >> 9, o = j & 511;
        g_woutt[j] = w_out[o*DIMD + d];
    } else if (i < ENC_CH*DIMD + DIMD*DEC_CH + DIMD*KCODES) {
        int j = i - (ENC_CH*DIMD + DIMD*DEC_CH);
        int d = j >> 13, k = j & 8191;
        g_et[j] = emb[k*DIMD + d];
    } else {
        int k = i - (ENC_CH*DIMD + DIMD*DEC_CH + DIMD*KCODES);
        if (k < KCODES) {
            float s = 0.f;
            #pragma unroll
            for (int d = 0; d < DIMD; d++) { float v = emb[k*DIMD + d]; s += v*v; }
            g_cn[k] = s;
        }
    }
}

// ---------------- encoder ----------------
__global__ __launch_bounds__(256) void enc_kernel(
    const float* __restrict__ x, const float* __restrict__ b_in)
{
    __shared__ float xs[64][64];
    __shared__ float ws[64][64];
    int tid = threadIdx.x;
    int tx = tid & 15, ty = tid >> 4;
    int n0 = blockIdx.x * 64;
    int b = n0 >> 10, hw0 = n0 & 1023;
    const float* xb = x + b*ENC_CH*1024 + hw0;

    float acc[4][4] = {};
    for (int c0 = 0; c0 < ENC_CH; c0 += 64) {
        for (int i = tid; i < 4096; i += 256) {
            int c = i >> 6, t = i & 63;
            xs[c][t] = xb[(c0 + c)*1024 + t];
            ws[c][t] = g_wint[(c0 + c)*64 + t];
        }
        __syncthreads();
        #pragma unroll 8
        for (int c = 0; c < 64; c++) {
            float4 a4 = *(const float4*)&xs[c][ty*4];
            float4 b4 = *(const float4*)&ws[c][tx*4];
            float a[4] = {a4.x,a4.y,a4.z,a4.w};
            float w[4] = {b4.x,b4.y,b4.z,b4.w};
            #pragma unroll
            for (int i2 = 0; i2 < 4; i2++)
                #pragma unroll
                for (int j = 0; j < 4; j++)
                    acc[i2][j] += a[i2]*w[j];
        }
        __syncthreads();
    }
    #pragma unroll
    for (int j = 0; j < 4; j++) {
        int d = tx*4 + j;
        float bb = b_in[d];
        #pragma unroll
        for (int i2 = 0; i2 < 4; i2++)
            g_zt[d*N_TOK + n0 + ty*4 + i2] = acc[i2][j] + bb;
    }
}

// ---------------- decode table ----------------
__global__ __launch_bounds__(256) void dec_table_kernel(const float* __restrict__ b_out)
{
    __shared__ float es[64][64];
    __shared__ float ws[64][128];
    int tid = threadIdx.x;
    int tx = tid & 15, ty = tid >> 4;
    int k0 = (blockIdx.x >> 2) * 64;
    int o0 = (blockIdx.x & 3) * 128;

    for (int i = tid; i < 4096; i += 256) {
        int d = i >> 6, c = i & 63;
        es[d][c] = g_et[d*KCODES + k0 + c];
    }
    for (int i = tid; i < 8192; i += 256) {
        int d = i >> 7, o = i & 127;
        ws[d][o] = g_woutt[d*DEC_CH + o0 + o];
    }
    __syncthreads();

    float acc[4][8] = {};
    #pragma unroll 8
    for (int d = 0; d < 64; d++) {
        float4 c4 = *(const float4*)&es[d][ty*4];
        float4 wa = *(const float4*)&ws[d][tx*8];
        float4 wb = *(const float4*)&ws[d][tx*8+4];
        float cv[4] = {c4.x,c4.y,c4.z,c4.w};
        float wv[8] = {wa.x,wa.y,wa.z,wa.w,wb.x,wb.y,wb.z,wb.w};
        #pragma unroll
        for (int i2 = 0; i2 < 4; i2++)
            #pragma unroll
            for (int j = 0; j < 8; j++)
                acc[i2][j] += cv[i2]*wv[j];
    }
    #pragma unroll
    for (int i2 = 0; i2 < 4; i2++) {
        int krow = k0 + ty*4 + i2;
        #pragma unroll
        for (int j = 0; j < 8; j++) {
            int o = o0 + tx*8 + j;
            g_dec[krow*DEC_CH + o] = acc[i2][j] + b_out[o];
        }
    }
}

// ---------------- distance + argmin: L1-wavefront-optimized tile -------------
// 512 blocks x 128 threads. Block (bid): tokens (bid>>1)*64, half (bid&1).
// Per-thread tile 4 tok x 8 codes: 3 LDS.128 per d-iter for 32 MACs
// (wf/MAC x0.75 vs previous 2 LDS.128 / 16 MACs).
// Warp map: cx=lane&7 (8 codes each), tg=lane>>3 (4 tok each), tw=warp (16 tok).
// All warps share chunk codes -> argmin reduce is cx-only (no smem merge).
#define DCHUNK  64
#define DNCH    (HALF_K/DCHUNK)   /* 64 */
__global__ __launch_bounds__(128, 4) void dist_kernel()
{
    __shared__ float zs[64][64];        // [d][t]           16KB
    __shared__ u64   es[2][64][32];     // [buf][d][pair]   32KB  (total 48KB)
    int tid = threadIdx.x;
    int lane = tid & 31, w = tid >> 5;
    int cx = lane & 7, tg = lane >> 3;
    int half  = blockIdx.x & 1;
    int n0    = (blockIdx.x >> 1) * 64;
    int cbase = half * HALF_K;

    for (int i = tid; i < 4096; i += 128) {
        int d = i >> 6, t = i & 63;
        zs[d][t] = g_zt[d*N_TOK + n0 + t];
    }
    int d0 = tid >> 5, p0 = tid & 31;   // es tile: 64 d x 32 pairs, 16 u64/thread
    #pragma unroll
    for (int j = 0; j < 16; j++)
        es[0][d0 + j*4][p0] = *(const u64*)(g_et + (d0 + j*4)*KCODES + cbase + 2*p0);
    __syncthreads();

    float best[4] = {FLT_MAX, FLT_MAX, FLT_MAX, FLT_MAX};
    int   bidx[4] = {0,0,0,0};
    int zcol = w*16 + tg*4;            // token column for this thread
    int ecol = cx*4;                   // first pair column for this thread

    for (int nc = 0; nc < DNCH; nc++) {
        int cur = nc & 1;
        int c0 = cbase + nc * DCHUNK;

        u64 r[16];
        if (nc + 1 < DNCH) {
            const float* src = g_et + c0 + DCHUNK + 2*p0;
            #pragma unroll
            for (int j = 0; j < 16; j++)
                r[j] = *(const u64*)(src + (d0 + j*4)*KCODES);
        }

        u64 acc[4][4];
        const float* cp = g_cn + c0 + cx*8;
        #pragma unroll
        for (int j = 0; j < 4; j++) {
            u64 cj = pack2(-0.5f*cp[2*j], -0.5f*cp[2*j+1]);
            acc[0][j] = cj; acc[1][j] = cj; acc[2][j] = cj; acc[3][j] = cj;
        }

        #pragma unroll 8
        for (int d = 0; d < 64; d++) {
            float4 z4 = *(const float4*)&zs[d][zcol];
            ulonglong2 ea = *(const ulonglong2*)&es[cur][d][ecol];
            ulonglong2 eb = *(const ulonglong2*)&es[cur][d][ecol + 2];
            u64 za0 = pack2(z4.x, z4.x);
            u64 za1 = pack2(z4.y, z4.y);
            u64 za2 = pack2(z4.z, z4.z);
            u64 za3 = pack2(z4.w, z4.w);
            fma2(acc[0][0], za0, ea.x); fma2(acc[0][1], za0, ea.y);
            fma2(acc[0][2], za0, eb.x); fma2(acc[0][3], za0, eb.y);
            fma2(acc[1][0], za1, ea.x); fma2(acc[1][1], za1, ea.y);
            fma2(acc[1][2], za1, eb.x); fma2(acc[1][3], za1, eb.y);
            fma2(acc[2][0], za2, ea.x); fma2(acc[2][1], za2, ea.y);
            fma2(acc[2][2], za2, eb.x); fma2(acc[2][3], za2, eb.y);
            fma2(acc[3][0], za3, ea.x); fma2(acc[3][1], za3, ea.y);
            fma2(acc[3][2], za3, eb.x); fma2(acc[3][3], za3, eb.y);
        }

        // score = -2*acc; per-thread codes ascending -> strict < keeps first-min
        #pragma unroll
        for (int i2 = 0; i2 < 4; i2++) {
            #pragma unroll
            for (int j = 0; j < 4; j++) {
                float lo, hi;
                unpack2(acc[i2][j], lo, hi);
                float slo = -2.0f*lo, shi = -2.0f*hi;
                int code = c0 + cx*8 + 2*j;
                if (slo < best[i2]) { best[i2] = slo; bidx[i2] = code; }
                if (shi < best[i2]) { best[i2] = shi; bidx[i2] = code + 1; }
            }
        }

        if (nc + 1 < DNCH) {
            #pragma unroll
            for (int j = 0; j < 16; j++)
                es[cur ^ 1][d0 + j*4][p0] = r[j];
        }
        __syncthreads();
    }

    // reduce over cx (8-lane groups); lexicographic (score, idx)
    #pragma unroll
    for (int off = 1; off < 8; off <<= 1) {
        #pragma unroll
        for (int i2 = 0; i2 < 4; i2++) {
            float ov = __shfl_xor_sync(0xffffffffu, best[i2], off);
            int   oi = __shfl_xor_sync(0xffffffffu, bidx[i2], off);
            if (ov < best[i2] || (ov == best[i2] && oi < bidx[i2])) {
                best[i2] = ov; bidx[i2] = oi;
            }
        }
    }
    if (cx == 0) {
        #pragma unroll
        for (int i2 = 0; i2 < 4; i2++) {
            int n = n0 + zcol + i2;
            g_bs[half*N_TOK + n] = best[i2];
            g_bi[half*N_TOK + n] = bidx[i2];
        }
    }
}

// ---------------- scatter + half-merge: out[b][o][hw] = g_dec[argmin][o] ------
__global__ __launch_bounds__(256) void scatter_kernel(
    float* __restrict__ out, float* __restrict__ idx_out)
{
    __shared__ int   sidx[16];
    __shared__ float buf[16][513];
    int tid = threadIdx.x;
    int n0 = blockIdx.x * 16;
    int b = n0 >> 10, hw0 = n0 & 1023;
    if (tid < 16) {
        int n = n0 + tid;
        float s0 = g_bs[n], s1 = g_bs[N_TOK + n];
        // half-1 indices are all larger: strict < keeps first-min semantics
        int idx = (s1 < s0) ? g_bi[N_TOK + n] : g_bi[n];
        sidx[tid] = idx;
        if (idx_out) idx_out[n] = (float)idx;
    }
    __syncthreads();
    for (int i = tid; i < 16*512; i += 256) {
        int t = i >> 9, o = i & 511;
        buf[t][o] = g_dec[sidx[t]*DEC_CH + o];
    }
    __syncthreads();
    float* ob = out + b*DEC_CH*1024 + hw0;
    for (int i = tid; i < 16*512; i += 256) {
        int o = i >> 4, t = i & 15;
        ob[o*1024 + t] = buf[t][o];
    }
}

// ---------------- launch ----------------
extern "C" void kernel_launch(void* const* d_in, const int* in_sizes, int n_in,
                              void* d_out, int out_size)
{
    const float* x     = (const float*)d_in[0];
    const float* w_in  = (const float*)d_in[1];
    const float* b_in  = (const float*)d_in[2];
    const float* emb   = (const float*)d_in[3];
    const float* w_out = (const float*)d_in[4];
    const float* b_out = (const float*)d_in[5];
    float* out = (float*)d_out;
    float* idx_out = (out_size >= OUT_MAIN + N_TOK) ? (out + OUT_MAIN) : nullptr;

    int prep_items = ENC_CH*DIMD + DIMD*DEC_CH + DIMD*KCODES + KCODES;
    prep_kernel<<<(prep_items + 255)/256, 256>>>(w_in, w_out, emb);
    enc_kernel<<<N_TOK/64, 256>>>(x, b_in);
    dec_table_kernel<<<(KCODES/64)*(DEC_CH/128), 256>>>(b_out);
    dist_kernel<<<2*(N_TOK/64), 128>>>();
    scatter_kernel<<<N_TOK/16, 256>>>(out, idx_out);
}